// round 13
// baseline (speedup 1.0000x reference)
#include <cuda_runtime.h>
#include <cuda_bf16.h>
#include <math.h>

// ---------------------------------------------------------------------------
// PatchQuantumGenerator: 5 qubits, 1 ancilla, 4 StronglyEntanglingLayers,
// 4 generators.
//   * circuit after RY-embedding = fixed 32x32 unitary U_g per generator
//   * embedded state is a real product state s[j]
//   * p0/max(p0) == probs[:16]/max(probs[:16])  (sum normalization cancels)
// => out[b, g*16+i] = |y_i|^2 / max_i |y_i|^2,  y = U_g[0:16,:] @ s(b)
// Kernel B: packed fp32x2 FMA, 2 elems/thread, output columns QUARTERED
// across thread quads (8 ull accs -> 8 blocks/SM). PDL overlap kept.
// ---------------------------------------------------------------------------

#define NQ 5
#define DIM 32
#define NOUT 16
#define G 4
#define L 4
#define NGATES (L * NQ)

// W layout per row j: 4 groups of 8 floats; group h = [Re(4h..4h+3), Im(4h..4h+3)]
__device__ float g_W[G][DIM][2 * NOUT];

typedef unsigned long long ull;

__device__ __forceinline__ ull ffma2(ull a, ull b, ull c) {
    ull d;
    asm("fma.rn.f32x2 %0, %1, %2, %3;" : "=l"(d) : "l"(a), "l"(b), "l"(c));
    return d;
}
__device__ __forceinline__ ull fmul2(ull a, ull b) {
    ull d;
    asm("mul.rn.f32x2 %0, %1, %2;" : "=l"(d) : "l"(a), "l"(b));
    return d;
}
__device__ __forceinline__ ull packab(float lo, float hi) {
    ull r;
    asm("mov.b64 %0, {%1, %2};" : "=l"(r) : "f"(lo), "f"(hi));
    return r;
}
__device__ __forceinline__ ull pack2(float x) {
    ull r;
    asm("mov.b64 %0, {%1, %1};" : "=l"(r) : "f"(x));
    return r;
}
__device__ __forceinline__ float2 unpack2(ull a) {
    float lo, hi;
    asm("mov.b64 {%0, %1}, %2;" : "=f"(lo), "=f"(hi) : "l"(a));
    return make_float2(lo, hi);
}

// ---------------------------------------------------------------------------
// Kernel A: build the 4 unitaries. One block per generator, 512 threads:
// thread = (col = t>>4, p = t&15); per-gate sync is warp-local.
// Ends with a PDL trigger so kernel B can launch while A drains.
// ---------------------------------------------------------------------------
__global__ void __launch_bounds__(512, 1)
build_unitaries_kernel(const float* __restrict__ w) {
    __shared__ float2 S[DIM][DIM];        // [column][amplitude], 8KB
    __shared__ float gm[NGATES][8];       // gate matrices

    const int g   = blockIdx.x;
    const int t   = threadIdx.x;          // 0..511
    const int col = t >> 4;               // 0..31
    const int p   = t & 15;               // pair index 0..15

    if (t < NGATES) {
        const int l = t / NQ, q = t % NQ;
        const float phi   = w[((g * L + l) * NQ + q) * 3 + 0];
        const float theta = w[((g * L + l) * NQ + q) * 3 + 1];
        const float omega = w[((g * L + l) * NQ + q) * 3 + 2];
        const float c = cosf(0.5f * theta);
        const float s = sinf(0.5f * theta);
        float epx, epy, emx, emy;
        sincosf(-0.5f * (phi + omega), &epy, &epx);   // ep = e^{-i(phi+omega)/2}
        sincosf(-0.5f * (phi - omega), &emy, &emx);   // em = e^{-i(phi-omega)/2}
        // m00 = ep*c ; m01 = -conj(em)*s ; m10 = em*s ; m11 = conj(ep)*c
        gm[t][0] = epx * c;   gm[t][1] = epy * c;
        gm[t][2] = -emx * s;  gm[t][3] = emy * s;
        gm[t][4] = emx * s;   gm[t][5] = emy * s;
        gm[t][6] = epx * c;   gm[t][7] = -epy * c;
    }

    S[col][p]      = make_float2(col == p      ? 1.0f : 0.0f, 0.0f);
    S[col][p + 16] = make_float2(col == p + 16 ? 1.0f : 0.0f, 0.0f);
    __syncthreads();

    float2* a = S[col];

    for (int l = 0; l < L; ++l) {
        for (int q = 0; q < NQ; ++q) {
            const float* m = gm[l * NQ + q];
            const int msk = 1 << (4 - q);
            const int lo  = p & (msk - 1);
            const int i0  = ((p & ~(msk - 1)) << 1) | lo;
            const int i1  = i0 | msk;
            const float2 a0 = a[i0], a1 = a[i1];
            float2 n0, n1;
            n0.x = m[0] * a0.x - m[1] * a0.y + m[2] * a1.x - m[3] * a1.y;
            n0.y = m[0] * a0.y + m[1] * a0.x + m[2] * a1.y + m[3] * a1.x;
            n1.x = m[4] * a0.x - m[5] * a0.y + m[6] * a1.x - m[7] * a1.y;
            n1.y = m[4] * a0.y + m[5] * a0.x + m[6] * a1.y + m[7] * a1.x;
            a[i0] = n0;
            a[i1] = n1;
            __syncwarp();
        }
        const int r = (l % (NQ - 1)) + 1;
        for (int q = 0; q < NQ; ++q) {
            const int cm = 1 << (4 - q);
            const int tq = (q + r) % NQ;
            const int tm = 1 << (4 - tq);
            const int lo = p & (tm - 1);
            const int i0 = ((p & ~(tm - 1)) << 1) | lo;   // target bit = 0
            if (i0 & cm) {
                const int i1 = i0 | tm;
                const float2 tmp = a[i0];
                a[i0] = a[i1];
                a[i1] = tmp;
            }
            __syncwarp();
        }
    }

    // output i = p: group = i>>2; Re -> group*8 + (i&3), Im -> group*8+4+(i&3)
    const int grp = p >> 2;
    const int i3  = p & 3;
    g_W[g][col][grp * 8 + i3]     = a[p].x;
    g_W[g][col][grp * 8 + 4 + i3] = a[p].y;

    __threadfence();
#if __CUDA_ARCH__ >= 900
    cudaTriggerProgrammaticLaunchCompletion();
#endif
}

// ---------------------------------------------------------------------------
// Kernel B: block = (tile of 64 batch elems) x (one g). 128 threads.
// Thread = (idx = tid>>2 -> elems b0, b0+32 ; h = tid&3 -> col quarter).
// Prologue runs BEFORE the PDL grid dependency sync.
// ---------------------------------------------------------------------------
__global__ void __launch_bounds__(128, 8)
qgen_main_kernel(const float* __restrict__ x, float* __restrict__ out, int B) {
    __shared__ float Wsh[DIM][2 * NOUT];   // 4 KB
    const int gsel = blockIdx.x & 3;
    const int tile = blockIdx.x >> 2;

    const int h   = threadIdx.x & 3;       // column quarter (4 cols)
    const int idx = threadIdx.x >> 2;      // 0..31
    const int b0r = tile * 64 + idx;
    const int b1r = b0r + 32;
    // clamp for the (never-taken in practice) tail; all threads stay alive
    const int b0 = min(b0r, B - 1);
    const int b1 = min(b1r, B - 1);

    // ---- prologue: packed (elem0, elem1) product-state prefix ----
    ull p3p[8], c3p, s3p, c4p, s4p;
    {
        float cc0[NQ], ss0[NQ], cc1[NQ], ss1[NQ];
        #pragma unroll
        for (int q = 0; q < NQ; ++q) {
            __sincosf(0.5f * x[b0 * NQ + q], &ss0[q], &cc0[q]);
            __sincosf(0.5f * x[b1 * NQ + q], &ss1[q], &cc1[q]);
        }
        ull f0c = packab(cc0[0], cc1[0]), f0s = packab(ss0[0], ss1[0]);
        ull f1c = packab(cc0[1], cc1[1]), f1s = packab(ss0[1], ss1[1]);
        ull f2c = packab(cc0[2], cc1[2]), f2s = packab(ss0[2], ss1[2]);
        c3p = packab(cc0[3], cc1[3]);  s3p = packab(ss0[3], ss1[3]);
        c4p = packab(cc0[4], cc1[4]);  s4p = packab(ss0[4], ss1[4]);
        ull p2p[4];
        p2p[0] = fmul2(f0c, f1c); p2p[1] = fmul2(f0c, f1s);
        p2p[2] = fmul2(f0s, f1c); p2p[3] = fmul2(f0s, f1s);
        #pragma unroll
        for (int k = 0; k < 4; ++k) {
            p3p[2 * k + 0] = fmul2(p2p[k], f2c);
            p3p[2 * k + 1] = fmul2(p2p[k], f2s);
        }
    }

    // ---- wait for kernel A's g_W, then stage it (all threads) ----
#if __CUDA_ARCH__ >= 900
    cudaGridDependencySynchronize();
#endif
    {
        // 4 KB = 256 float4; 128 threads -> 2 each
        const float4* src = reinterpret_cast<const float4*>(&g_W[gsel][0][0]);
        float4* dst = reinterpret_cast<float4*>(&Wsh[0][0]);
        dst[threadIdx.x]       = src[threadIdx.x];
        dst[threadIdx.x + 128] = src[threadIdx.x + 128];
    }
    __syncthreads();

    // acc per elem (this quarter = cols 4h..4h+3):
    // a[0]=Re(4h,4h+1) a[1]=Re(4h+2,4h+3) a[2]=Im(4h,4h+1) a[3]=Im(4h+2,4h+3)
    ull a0[4], a1[4];
    #pragma unroll
    for (int k = 0; k < 4; ++k) { a0[k] = 0ULL; a1[k] = 0ULL; }

    const int hoff = h * 8;   // float offset of this quarter's group in a row

    #pragma unroll
    for (int j4 = 0; j4 < 16; ++j4) {
        // p4 = p3[j4>>1] * (j4&1 ? s3 : c3); vA = p4*c4, vB = p4*s4 (packed)
        const ull p4p = fmul2(p3p[j4 >> 1], (j4 & 1) ? s3p : c3p);
        const float2 vA = unpack2(fmul2(p4p, c4p));
        const float2 vB = unpack2(fmul2(p4p, s4p));
        const ull sA0 = pack2(vA.x), sA1 = pack2(vA.y);
        const ull sB0 = pack2(vB.x), sB1 = pack2(vB.y);
        const ulonglong2* rA = reinterpret_cast<const ulonglong2*>(&Wsh[2 * j4][hoff]);
        const ulonglong2* rB = reinterpret_cast<const ulonglong2*>(&Wsh[2 * j4 + 1][hoff]);
        {
            const ulonglong2 wRe = rA[0];   // Re pairs
            const ulonglong2 wIm = rA[1];   // Im pairs
            a0[0] = ffma2(wRe.x, sA0, a0[0]); a0[1] = ffma2(wRe.y, sA0, a0[1]);
            a0[2] = ffma2(wIm.x, sA0, a0[2]); a0[3] = ffma2(wIm.y, sA0, a0[3]);
            a1[0] = ffma2(wRe.x, sA1, a1[0]); a1[1] = ffma2(wRe.y, sA1, a1[1]);
            a1[2] = ffma2(wIm.x, sA1, a1[2]); a1[3] = ffma2(wIm.y, sA1, a1[3]);
        }
        {
            const ulonglong2 wRe = rB[0];
            const ulonglong2 wIm = rB[1];
            a0[0] = ffma2(wRe.x, sB0, a0[0]); a0[1] = ffma2(wRe.y, sB0, a0[1]);
            a0[2] = ffma2(wIm.x, sB0, a0[2]); a0[3] = ffma2(wIm.y, sB0, a0[3]);
            a1[0] = ffma2(wRe.x, sB1, a1[0]); a1[1] = ffma2(wRe.y, sB1, a1[1]);
            a1[2] = ffma2(wIm.x, sB1, a1[2]); a1[3] = ffma2(wIm.y, sB1, a1[3]);
        }
    }

    // epilogue: outputs 4h..4h+3 per element; max over the 4-thread quad
    // via shfl.xor(1) + shfl.xor(2); one float4 store per element.
    #pragma unroll
    for (int e = 0; e < 2; ++e) {
        const ull* a = e ? a1 : a0;
        const int br = e ? b1r : b0r;
        float pr[4];
        {
            const float2 re0 = unpack2(a[0]);   // cols 4h, 4h+1
            const float2 im0 = unpack2(a[2]);
            const float2 re1 = unpack2(a[1]);   // cols 4h+2, 4h+3
            const float2 im1 = unpack2(a[3]);
            pr[0] = re0.x * re0.x + im0.x * im0.x;
            pr[1] = re0.y * re0.y + im0.y * im0.y;
            pr[2] = re1.x * re1.x + im1.x * im1.x;
            pr[3] = re1.y * re1.y + im1.y * im1.y;
        }
        float mx = fmaxf(fmaxf(pr[0], pr[1]), fmaxf(pr[2], pr[3]));
        mx = fmaxf(mx, __shfl_xor_sync(0xffffffffu, mx, 1));
        mx = fmaxf(mx, __shfl_xor_sync(0xffffffffu, mx, 2));
        const float inv = 1.0f / mx;
        if (br < B) {
            float4 o;
            o.x = pr[0] * inv;
            o.y = pr[1] * inv;
            o.z = pr[2] * inv;
            o.w = pr[3] * inv;
            *reinterpret_cast<float4*>(out + (size_t)br * (G * NOUT) + gsel * NOUT + 4 * h) = o;
        }
    }
}

extern "C" void kernel_launch(void* const* d_in, const int* in_sizes, int n_in,
                              void* d_out, int out_size) {
    const float* x = (const float*)d_in[0];        // [B, 5]
    const float* w = (const float*)d_in[1];        // [4, 4, 5, 3]
    float* out = (float*)d_out;                    // [B, 64]
    const int B = in_sizes[0] / NQ;

    build_unitaries_kernel<<<G, 512>>>(w);

    const int tiles = (B + 63) / 64;               // 64 elements per tile

    cudaLaunchConfig_t cfg = {};
    cfg.gridDim  = dim3(tiles * G);
    cfg.blockDim = dim3(128);
    cfg.dynamicSmemBytes = 0;
    cfg.stream = 0;
    cudaLaunchAttribute attr[1];
    attr[0].id = cudaLaunchAttributeProgrammaticStreamSerialization;
    attr[0].val.programmaticStreamSerializationAllowed = 1;
    cfg.attrs = attr;
    cfg.numAttrs = 1;
    cudaLaunchKernelEx(&cfg, qgen_main_kernel, x, out, B);
}